// round 4
// baseline (speedup 1.0000x reference)
#include <cuda_runtime.h>
#include <cuda_bf16.h>

#define N_NODES 50000
#define N_EDGES 800000
#define IN_DIM  64
#define HID_DIM 128
#define OUT_DIM 64

typedef unsigned long long u64;

// ---------------- packed f32x2 helpers (Blackwell FFMA2) ----------------
__device__ __forceinline__ u64 pk(float x, float y) {
    u64 r; asm("mov.b64 %0, {%1, %2};" : "=l"(r) : "f"(x), "f"(y)); return r;
}
__device__ __forceinline__ u64 dup2(float x) {
    u64 r; asm("mov.b64 %0, {%1, %2};" : "=l"(r) : "f"(x), "f"(x)); return r;
}
__device__ __forceinline__ void fma2(u64& d, u64 a, u64 b) {
    asm("fma.rn.f32x2 %0, %1, %2, %3;" : "=l"(d) : "l"(a), "l"(b), "l"(d));
}
__device__ __forceinline__ float2 unpk(u64 a) {
    float2 f; asm("mov.b64 {%0, %1}, %2;" : "=f"(f.x), "=f"(f.y) : "l"(a)); return f;
}

// ---------------- scratch (static device globals; no allocation) ----------------
__device__ __align__(16) float g_az[N_NODES * IN_DIM];    // A_norm @ z
__device__ __align__(16) float g_h [N_NODES * HID_DIM];   // relu(az @ W1 + b1)
__device__ __align__(16) float g_hw[N_NODES * OUT_DIM];   // h @ W2
__device__ float g_dinv[N_NODES];
__device__ int   g_cnt[N_NODES];
__device__ int   g_cur[N_NODES];
__device__ int   g_rowptr[N_NODES + 1];
__device__ int   g_esrc[N_EDGES];
__device__ int   g_lb[64];                  // lookback: (state<<28)|value

// ---------------- init ----------------
__global__ void k_init() {
    int i = blockIdx.x * blockDim.x + threadIdx.x;
    if (i < N_NODES) g_cnt[i] = 0;
    if (i < 64) g_lb[i] = 0;
}

__global__ void k_count(const int* __restrict__ ei) {
    int e = blockIdx.x * blockDim.x + threadIdx.x;
    if (e < N_EDGES) atomicAdd(&g_cnt[ei[N_EDGES + e]], 1);
}

// ---------------- single-kernel decoupled-lookback scan + dinv + cursors ----------------
__global__ __launch_bounds__(1024) void k_scanlb() {
    __shared__ int s[1024];
    __shared__ int s_prefix;
    int b = blockIdx.x, t = threadIdx.x;
    int i = b * 1024 + t;
    int v = (i < N_NODES) ? g_cnt[i] : 0;
    s[t] = v;
    __syncthreads();
    // Hillis-Steele inclusive scan
    for (int off = 1; off < 1024; off <<= 1) {
        int tv = 0;
        if (t >= off) tv = s[t - off];
        __syncthreads();
        s[t] += tv;
        __syncthreads();
    }
    int total = s[1023];
    if (t == 0) {
        if (b > 0) atomicExch(&g_lb[b], (1 << 28) | total);   // aggregate ready
        int prefix = 0;
        for (int j = b - 1; j >= 0; ) {
            int f = atomicAdd(&g_lb[j], 0);
            int st = f >> 28;
            if (st == 2) { prefix += f & 0x0FFFFFFF; break; }
            if (st == 1) { prefix += f & 0x0FFFFFFF; j--; }
            // st == 0: spin
        }
        atomicExch(&g_lb[b], (2 << 28) | (prefix + total));    // inclusive ready
        s_prefix = prefix;
    }
    __syncthreads();
    if (i < N_NODES) {
        int incl = s[t] + s_prefix;
        g_rowptr[i + 1] = incl;
        g_cur[i] = incl - v;
        g_dinv[i] = rsqrtf((float)(v + 1));   // +1 self-loop
    }
    if (i == 0) g_rowptr[0] = 0;
}

__global__ void k_scatter(const int* __restrict__ ei) {
    int e = blockIdx.x * blockDim.x + threadIdx.x;
    if (e < N_EDGES) {
        int s = ei[e];
        int d = ei[N_EDGES + e];
        int pos = atomicAdd(&g_cur[d], 1);
        g_esrc[pos] = s;
    }
}

// ---------------- Aggregation 0: az = A_norm @ z   (64-dim, f32x2/lane) ----------------
__global__ __launch_bounds__(256) void k_aggz(const float* __restrict__ z) {
    int gw   = (blockIdx.x * blockDim.x + threadIdx.x) >> 5;
    int lane = threadIdx.x & 31;
    if (gw >= N_NODES) return;
    float di = g_dinv[gw];
    u64 self = ((const u64*)z)[gw * 32 + lane];
    u64 acc  = 0;                              // bits of {0.f, 0.f}
    fma2(acc, dup2(di * di), self);

    int beg = g_rowptr[gw], end = g_rowptr[gw + 1];
    int e = beg;
    for (; e + 4 <= end; e += 4) {
        int i0 = __ldg(&g_esrc[e]);
        int i1 = __ldg(&g_esrc[e + 1]);
        int i2 = __ldg(&g_esrc[e + 2]);
        int i3 = __ldg(&g_esrc[e + 3]);
        u64 w0 = dup2(__ldg(&g_dinv[i0]) * di);
        u64 w1 = dup2(__ldg(&g_dinv[i1]) * di);
        u64 w2 = dup2(__ldg(&g_dinv[i2]) * di);
        u64 w3 = dup2(__ldg(&g_dinv[i3]) * di);
        u64 v0 = ((const u64*)z)[i0 * 32 + lane];
        u64 v1 = ((const u64*)z)[i1 * 32 + lane];
        u64 v2 = ((const u64*)z)[i2 * 32 + lane];
        u64 v3 = ((const u64*)z)[i3 * 32 + lane];
        fma2(acc, w0, v0); fma2(acc, w1, v1);
        fma2(acc, w2, v2); fma2(acc, w3, v3);
    }
    for (; e < end; e++) {
        int s = __ldg(&g_esrc[e]);
        u64 wv = dup2(__ldg(&g_dinv[s]) * di);
        fma2(acc, wv, ((const u64*)z)[s * 32 + lane]);
    }
    ((u64*)g_az)[gw * 32 + lane] = acc;
}

// ---------------- GEMM 1 (fused bias+relu): h = relu(az @ W1 + b1) ----------------
// FFMA2: accumulate even-k / odd-k partials packed; lane owns cols {2l,2l+1,2l+64,2l+65}
__global__ __launch_bounds__(128) void k_gemm1(const float* __restrict__ W1,
                                               const float* __restrict__ b1) {
    __shared__ u64 sW[32 * 128];                    // 32 KB: {W1[2t][j], W1[2t+1][j]}
    __shared__ __align__(16) float sX[4][IN_DIM];
    int lane = threadIdx.x & 31;
    int w    = threadIdx.x >> 5;
    for (int idx = threadIdx.x; idx < 32 * 128; idx += 128) {
        int t = idx >> 7, j = idx & 127;
        sW[idx] = pk(W1[(2 * t) * 128 + j], W1[(2 * t + 1) * 128 + j]);
    }
    __syncthreads();
    int c0 = 2 * lane;
    float2 bA = *(const float2*)&b1[c0];
    float2 bB = *(const float2*)&b1[c0 + 64];

    for (int node = blockIdx.x * 4 + w; node < N_NODES; node += gridDim.x * 4) {
        ((float2*)sX[w])[lane] = ((const float2*)(g_az + node * IN_DIM))[lane];
        __syncwarp();
        u64 a0 = pk(bA.x, 0.f), a1 = pk(bA.y, 0.f);
        u64 a2 = pk(bB.x, 0.f), a3 = pk(bB.y, 0.f);
        #pragma unroll 8
        for (int t = 0; t < 32; t++) {
            u64 xp = *(const u64*)&sX[w][2 * t];
            ulonglong2 wA = *(const ulonglong2*)&sW[t * 128 + c0];
            ulonglong2 wB = *(const ulonglong2*)&sW[t * 128 + c0 + 64];
            fma2(a0, xp, wA.x); fma2(a1, xp, wA.y);
            fma2(a2, xp, wB.x); fma2(a3, xp, wB.y);
        }
        float2 f0 = unpk(a0), f1 = unpk(a1), f2 = unpk(a2), f3 = unpk(a3);
        float2 r01 = make_float2(fmaxf(f0.x + f0.y, 0.f), fmaxf(f1.x + f1.y, 0.f));
        float2 r23 = make_float2(fmaxf(f2.x + f2.y, 0.f), fmaxf(f3.x + f3.y, 0.f));
        ((float2*)(g_h + node * HID_DIM))[lane] = r01;
        ((float2*)(g_h + node * HID_DIM + 64))[lane] = r23;
        __syncwarp();
    }
}

// ---------------- GEMM 2: hw = h @ W2 ----------------
__global__ __launch_bounds__(128) void k_gemm2(const float* __restrict__ W2) {
    __shared__ u64 sW[64 * 64];                     // 32 KB: {W2[2t][j], W2[2t+1][j]}
    __shared__ __align__(16) float sX[4][HID_DIM];
    int lane = threadIdx.x & 31;
    int w    = threadIdx.x >> 5;
    for (int idx = threadIdx.x; idx < 64 * 64; idx += 128) {
        int t = idx >> 6, j = idx & 63;
        sW[idx] = pk(W2[(2 * t) * 64 + j], W2[(2 * t + 1) * 64 + j]);
    }
    __syncthreads();
    int c0 = 2 * lane;

    for (int node = blockIdx.x * 4 + w; node < N_NODES; node += gridDim.x * 4) {
        ((float4*)sX[w])[lane] = ((const float4*)(g_h + node * HID_DIM))[lane];
        __syncwarp();
        u64 a0 = 0, a1 = 0;
        #pragma unroll 8
        for (int t = 0; t < 64; t++) {
            u64 xp = *(const u64*)&sX[w][2 * t];
            ulonglong2 wA = *(const ulonglong2*)&sW[t * 64 + c0];
            fma2(a0, xp, wA.x); fma2(a1, xp, wA.y);
        }
        float2 f0 = unpk(a0), f1 = unpk(a1);
        ((float2*)(g_hw + node * OUT_DIM))[lane] = make_float2(f0.x + f0.y, f1.x + f1.y);
        __syncwarp();
    }
}

// ---------------- Aggregation 2: out = A_norm @ hw + b2 ----------------
__global__ __launch_bounds__(256) void k_agg2(const float* __restrict__ b2,
                                              float* __restrict__ out) {
    int gw   = (blockIdx.x * blockDim.x + threadIdx.x) >> 5;
    int lane = threadIdx.x & 31;
    if (gw >= N_NODES) return;
    float di = g_dinv[gw];
    u64 self = ((const u64*)g_hw)[gw * 32 + lane];
    float2 bv = ((const float2*)b2)[lane];
    u64 acc = pk(bv.x, bv.y);
    fma2(acc, dup2(di * di), self);

    int beg = g_rowptr[gw], end = g_rowptr[gw + 1];
    int e = beg;
    for (; e + 4 <= end; e += 4) {
        int i0 = __ldg(&g_esrc[e]);
        int i1 = __ldg(&g_esrc[e + 1]);
        int i2 = __ldg(&g_esrc[e + 2]);
        int i3 = __ldg(&g_esrc[e + 3]);
        u64 w0 = dup2(__ldg(&g_dinv[i0]) * di);
        u64 w1 = dup2(__ldg(&g_dinv[i1]) * di);
        u64 w2 = dup2(__ldg(&g_dinv[i2]) * di);
        u64 w3 = dup2(__ldg(&g_dinv[i3]) * di);
        u64 v0 = ((const u64*)g_hw)[i0 * 32 + lane];
        u64 v1 = ((const u64*)g_hw)[i1 * 32 + lane];
        u64 v2 = ((const u64*)g_hw)[i2 * 32 + lane];
        u64 v3 = ((const u64*)g_hw)[i3 * 32 + lane];
        fma2(acc, w0, v0); fma2(acc, w1, v1);
        fma2(acc, w2, v2); fma2(acc, w3, v3);
    }
    for (; e < end; e++) {
        int s = __ldg(&g_esrc[e]);
        u64 wv = dup2(__ldg(&g_dinv[s]) * di);
        fma2(acc, wv, ((const u64*)g_hw)[s * 32 + lane]);
    }
    ((u64*)out)[gw * 32 + lane] = acc;
}

// ---------------- launch ----------------
extern "C" void kernel_launch(void* const* d_in, const int* in_sizes, int n_in,
                              void* d_out, int out_size) {
    const float* z  = nullptr;
    const int*   ei = nullptr;
    const float* W1 = nullptr;
    const float* W2 = nullptr;
    const float* b1 = nullptr;
    const float* b2 = nullptr;
    for (int i = 0; i < n_in; i++) {
        int n = in_sizes[i];
        if      (n == N_NODES * IN_DIM)  z  = (const float*)d_in[i];
        else if (n == 2 * N_EDGES)       ei = (const int*)d_in[i];
        else if (n == IN_DIM * HID_DIM) { if (!W1) W1 = (const float*)d_in[i]; else W2 = (const float*)d_in[i]; }
        else if (n == HID_DIM)           b1 = (const float*)d_in[i];
        else if (n == OUT_DIM)           b2 = (const float*)d_in[i];
    }
    float* out = (float*)d_out;

    const int gN  = (N_NODES + 255) / 256;
    const int gE  = (N_EDGES + 255) / 256;
    const int gSC = (N_NODES + 1023) / 1024;           // 49 scan blocks
    const int gW  = (N_NODES * 32 + 255) / 256;         // warp-per-node grids

    k_init   <<<gN, 256>>>();
    k_count  <<<gE, 256>>>(ei);
    k_scanlb <<<gSC, 1024>>>();
    k_scatter<<<gE, 256>>>(ei);

    k_aggz <<<gW, 256>>>(z);
    k_gemm1<<<1024, 128>>>(W1, b1);
    k_gemm2<<<1024, 128>>>(W2);
    k_agg2 <<<gW, 256>>>(b2, out);
}

// round 5
// speedup vs baseline: 1.5674x; 1.5674x over previous
#include <cuda_runtime.h>
#include <cuda_bf16.h>

#define N_NODES 50000
#define N_EDGES 800000
#define IN_DIM  64
#define HID_DIM 128
#define OUT_DIM 64

typedef unsigned long long u64;

// ---------------- packed f32x2 helpers (Blackwell FFMA2) ----------------
__device__ __forceinline__ u64 pk(float x, float y) {
    u64 r; asm("mov.b64 %0, {%1, %2};" : "=l"(r) : "f"(x), "f"(y)); return r;
}
__device__ __forceinline__ u64 dup2(float x) {
    u64 r; asm("mov.b64 %0, {%1, %2};" : "=l"(r) : "f"(x), "f"(x)); return r;
}
__device__ __forceinline__ void fma2(u64& d, u64 a, u64 b) {
    asm("fma.rn.f32x2 %0, %1, %2, %3;" : "=l"(d) : "l"(a), "l"(b), "l"(d));
}
__device__ __forceinline__ float2 unpk(u64 a) {
    float2 f; asm("mov.b64 {%0, %1}, %2;" : "=f"(f.x), "=f"(f.y) : "l"(a)); return f;
}

// ---------------- scratch ----------------
__device__ __align__(16) float g_az[N_NODES * IN_DIM];
__device__ __align__(16) float g_h [N_NODES * HID_DIM];
__device__ __align__(16) float g_hw[N_NODES * OUT_DIM];
__device__ float g_dinv[N_NODES];
__device__ int   g_cnt[N_NODES];
__device__ int   g_cur[N_NODES];
__device__ int   g_rowptr[N_NODES + 1];
__device__ int   g_esrc[N_EDGES];
__device__ int   g_lb[64];

// ---------------- init ----------------
__global__ void k_init() {
    int i = blockIdx.x * blockDim.x + threadIdx.x;
    if (i < N_NODES) g_cnt[i] = 0;
    if (i < 64) g_lb[i] = 0;
}

__global__ void k_count(const int* __restrict__ ei) {
    int e = blockIdx.x * blockDim.x + threadIdx.x;
    if (e < N_EDGES) atomicAdd(&g_cnt[ei[N_EDGES + e]], 1);
}

// ---------------- single-kernel decoupled-lookback scan + dinv + cursors ----------------
__global__ __launch_bounds__(1024) void k_scanlb() {
    __shared__ int s[1024];
    __shared__ int s_prefix;
    int b = blockIdx.x, t = threadIdx.x;
    int i = b * 1024 + t;
    int v = (i < N_NODES) ? g_cnt[i] : 0;
    s[t] = v;
    __syncthreads();
    for (int off = 1; off < 1024; off <<= 1) {
        int tv = 0;
        if (t >= off) tv = s[t - off];
        __syncthreads();
        s[t] += tv;
        __syncthreads();
    }
    int total = s[1023];
    if (t == 0) {
        if (b > 0) atomicExch(&g_lb[b], (1 << 28) | total);
        int prefix = 0;
        for (int j = b - 1; j >= 0; ) {
            int f = atomicAdd(&g_lb[j], 0);
            int st = f >> 28;
            if (st == 2) { prefix += f & 0x0FFFFFFF; break; }
            if (st == 1) { prefix += f & 0x0FFFFFFF; j--; }
        }
        atomicExch(&g_lb[b], (2 << 28) | (prefix + total));
        s_prefix = prefix;
    }
    __syncthreads();
    if (i < N_NODES) {
        int incl = s[t] + s_prefix;
        g_rowptr[i + 1] = incl;
        g_cur[i] = incl - v;
        g_dinv[i] = rsqrtf((float)(v + 1));
    }
    if (i == 0) g_rowptr[0] = 0;
}

__global__ void k_scatter(const int* __restrict__ ei) {
    int e = blockIdx.x * blockDim.x + threadIdx.x;
    if (e < N_EDGES) {
        int s = ei[e];
        int d = ei[N_EDGES + e];
        int pos = atomicAdd(&g_cur[d], 1);
        g_esrc[pos] = s;
    }
}

// ---------------- Aggregation 0: az = A_norm @ z ----------------
__global__ __launch_bounds__(256) void k_aggz(const float* __restrict__ z) {
    int gw   = (blockIdx.x * blockDim.x + threadIdx.x) >> 5;
    int lane = threadIdx.x & 31;
    if (gw >= N_NODES) return;
    float di = g_dinv[gw];
    u64 self = ((const u64*)z)[gw * 32 + lane];
    u64 acc  = 0;
    fma2(acc, dup2(di * di), self);

    int beg = g_rowptr[gw], end = g_rowptr[gw + 1];
    int e = beg;
    for (; e + 4 <= end; e += 4) {
        int i0 = __ldg(&g_esrc[e]);
        int i1 = __ldg(&g_esrc[e + 1]);
        int i2 = __ldg(&g_esrc[e + 2]);
        int i3 = __ldg(&g_esrc[e + 3]);
        u64 w0 = dup2(__ldg(&g_dinv[i0]) * di);
        u64 w1 = dup2(__ldg(&g_dinv[i1]) * di);
        u64 w2 = dup2(__ldg(&g_dinv[i2]) * di);
        u64 w3 = dup2(__ldg(&g_dinv[i3]) * di);
        u64 v0 = ((const u64*)z)[i0 * 32 + lane];
        u64 v1 = ((const u64*)z)[i1 * 32 + lane];
        u64 v2 = ((const u64*)z)[i2 * 32 + lane];
        u64 v3 = ((const u64*)z)[i3 * 32 + lane];
        fma2(acc, w0, v0); fma2(acc, w1, v1);
        fma2(acc, w2, v2); fma2(acc, w3, v3);
    }
    for (; e < end; e++) {
        int s = __ldg(&g_esrc[e]);
        u64 wv = dup2(__ldg(&g_dinv[s]) * di);
        fma2(acc, wv, ((const u64*)z)[s * 32 + lane]);
    }
    ((u64*)g_az)[gw * 32 + lane] = acc;
}

// ---------------- GEMM 1: h = relu(az @ W1 + b1), 8 nodes per warp ----------------
__global__ __launch_bounds__(128) void k_gemm1(const float* __restrict__ W1,
                                               const float* __restrict__ b1) {
    __shared__ u64 sW[32 * 128];                       // 32 KB
    __shared__ __align__(16) float sX[4][8][IN_DIM];   // 8 KB
    int lane = threadIdx.x & 31;
    int w    = threadIdx.x >> 5;
    for (int idx = threadIdx.x; idx < 32 * 128; idx += 128) {
        int t = idx >> 7, j = idx & 127;
        sW[idx] = pk(W1[(2 * t) * 128 + j], W1[(2 * t + 1) * 128 + j]);
    }
    __syncthreads();
    int c0 = 2 * lane;
    float2 bA = *(const float2*)&b1[c0];
    float2 bB = *(const float2*)&b1[c0 + 64];

    int warpId = blockIdx.x * 4 + w;
    int nWarps = gridDim.x * 4;
    for (int base = warpId * 8; base < N_NODES; base += nWarps * 8) {
        // stage 8 nodes of x (8 x 256B); lane loads 4 float4s
        #pragma unroll
        for (int q = 0; q < 4; q++) {
            int idx = lane + 32 * q;                   // 0..127
            int n = idx >> 4, r = idx & 15;
            ((float4*)sX[w][n])[r] = ((const float4*)(g_az + (size_t)(base + n) * IN_DIM))[r];
        }
        __syncwarp();
        u64 aA0[8], aA1[8], aB0[8], aB1[8];
        #pragma unroll
        for (int n = 0; n < 8; n++) {
            aA0[n] = pk(bA.x, 0.f); aA1[n] = pk(bA.y, 0.f);
            aB0[n] = pk(bB.x, 0.f); aB1[n] = pk(bB.y, 0.f);
        }
        #pragma unroll 4
        for (int t = 0; t < 32; t++) {
            ulonglong2 wA = *(const ulonglong2*)&sW[t * 128 + c0];
            ulonglong2 wB = *(const ulonglong2*)&sW[t * 128 + c0 + 64];
            #pragma unroll
            for (int n = 0; n < 8; n++) {
                u64 xp = *(const u64*)&sX[w][n][2 * t];
                fma2(aA0[n], xp, wA.x); fma2(aA1[n], xp, wA.y);
                fma2(aB0[n], xp, wB.x); fma2(aB1[n], xp, wB.y);
            }
        }
        #pragma unroll
        for (int n = 0; n < 8; n++) {
            float2 f0 = unpk(aA0[n]), f1 = unpk(aA1[n]);
            float2 f2 = unpk(aB0[n]), f3 = unpk(aB1[n]);
            float* hrow = g_h + (size_t)(base + n) * HID_DIM;
            ((float2*)hrow)[lane] =
                make_float2(fmaxf(f0.x + f0.y, 0.f), fmaxf(f1.x + f1.y, 0.f));
            ((float2*)(hrow + 64))[lane] =
                make_float2(fmaxf(f2.x + f2.y, 0.f), fmaxf(f3.x + f3.y, 0.f));
        }
        __syncwarp();
    }
}

// ---------------- GEMM 2: hw = h @ W2, 8 nodes per warp ----------------
__global__ __launch_bounds__(128) void k_gemm2(const float* __restrict__ W2) {
    __shared__ u64 sW[64 * 64];                         // 32 KB
    __shared__ __align__(16) float sX[4][8][HID_DIM];   // 16 KB
    int lane = threadIdx.x & 31;
    int w    = threadIdx.x >> 5;
    for (int idx = threadIdx.x; idx < 64 * 64; idx += 128) {
        int t = idx >> 6, j = idx & 63;
        sW[idx] = pk(W2[(2 * t) * 64 + j], W2[(2 * t + 1) * 64 + j]);
    }
    __syncthreads();
    int c0 = 2 * lane;

    int warpId = blockIdx.x * 4 + w;
    int nWarps = gridDim.x * 4;
    for (int base = warpId * 8; base < N_NODES; base += nWarps * 8) {
        // stage 8 nodes of h (8 x 512B); lane loads 8 float4s
        #pragma unroll
        for (int q = 0; q < 8; q++) {
            int idx = lane + 32 * q;                    // 0..255
            int n = idx >> 5, r = idx & 31;
            ((float4*)sX[w][n])[r] = ((const float4*)(g_h + (size_t)(base + n) * HID_DIM))[r];
        }
        __syncwarp();
        u64 a0[8], a1[8];
        #pragma unroll
        for (int n = 0; n < 8; n++) { a0[n] = 0; a1[n] = 0; }
        #pragma unroll 8
        for (int t = 0; t < 64; t++) {
            ulonglong2 wA = *(const ulonglong2*)&sW[t * 64 + c0];
            #pragma unroll
            for (int n = 0; n < 8; n++) {
                u64 xp = *(const u64*)&sX[w][n][2 * t];
                fma2(a0[n], xp, wA.x); fma2(a1[n], xp, wA.y);
            }
        }
        #pragma unroll
        for (int n = 0; n < 8; n++) {
            float2 f0 = unpk(a0[n]), f1 = unpk(a1[n]);
            ((float2*)(g_hw + (size_t)(base + n) * OUT_DIM))[lane] =
                make_float2(f0.x + f0.y, f1.x + f1.y);
        }
        __syncwarp();
    }
}

// ---------------- Aggregation 2: out = A_norm @ hw + b2 ----------------
__global__ __launch_bounds__(256) void k_agg2(const float* __restrict__ b2,
                                              float* __restrict__ out) {
    int gw   = (blockIdx.x * blockDim.x + threadIdx.x) >> 5;
    int lane = threadIdx.x & 31;
    if (gw >= N_NODES) return;
    float di = g_dinv[gw];
    u64 self = ((const u64*)g_hw)[gw * 32 + lane];
    float2 bv = ((const float2*)b2)[lane];
    u64 acc = pk(bv.x, bv.y);
    fma2(acc, dup2(di * di), self);

    int beg = g_rowptr[gw], end = g_rowptr[gw + 1];
    int e = beg;
    for (; e + 4 <= end; e += 4) {
        int i0 = __ldg(&g_esrc[e]);
        int i1 = __ldg(&g_esrc[e + 1]);
        int i2 = __ldg(&g_esrc[e + 2]);
        int i3 = __ldg(&g_esrc[e + 3]);
        u64 w0 = dup2(__ldg(&g_dinv[i0]) * di);
        u64 w1 = dup2(__ldg(&g_dinv[i1]) * di);
        u64 w2 = dup2(__ldg(&g_dinv[i2]) * di);
        u64 w3 = dup2(__ldg(&g_dinv[i3]) * di);
        u64 v0 = ((const u64*)g_hw)[i0 * 32 + lane];
        u64 v1 = ((const u64*)g_hw)[i1 * 32 + lane];
        u64 v2 = ((const u64*)g_hw)[i2 * 32 + lane];
        u64 v3 = ((const u64*)g_hw)[i3 * 32 + lane];
        fma2(acc, w0, v0); fma2(acc, w1, v1);
        fma2(acc, w2, v2); fma2(acc, w3, v3);
    }
    for (; e < end; e++) {
        int s = __ldg(&g_esrc[e]);
        u64 wv = dup2(__ldg(&g_dinv[s]) * di);
        fma2(acc, wv, ((const u64*)g_hw)[s * 32 + lane]);
    }
    ((u64*)out)[gw * 32 + lane] = acc;
}

// ---------------- launch ----------------
extern "C" void kernel_launch(void* const* d_in, const int* in_sizes, int n_in,
                              void* d_out, int out_size) {
    const float* z  = nullptr;
    const int*   ei = nullptr;
    const float* W1 = nullptr;
    const float* W2 = nullptr;
    const float* b1 = nullptr;
    const float* b2 = nullptr;
    for (int i = 0; i < n_in; i++) {
        int n = in_sizes[i];
        if      (n == N_NODES * IN_DIM)  z  = (const float*)d_in[i];
        else if (n == 2 * N_EDGES)       ei = (const int*)d_in[i];
        else if (n == IN_DIM * HID_DIM) { if (!W1) W1 = (const float*)d_in[i]; else W2 = (const float*)d_in[i]; }
        else if (n == HID_DIM)           b1 = (const float*)d_in[i];
        else if (n == OUT_DIM)           b2 = (const float*)d_in[i];
    }
    float* out = (float*)d_out;

    const int gN  = (N_NODES + 255) / 256;
    const int gE  = (N_EDGES + 255) / 256;
    const int gSC = (N_NODES + 1023) / 1024;
    const int gW  = (N_NODES * 32 + 255) / 256;
    const int gG  = 1563;   // 6252 warps: one 8-node batch per warp

    k_init   <<<gN, 256>>>();
    k_count  <<<gE, 256>>>(ei);
    k_scanlb <<<gSC, 1024>>>();
    k_scatter<<<gE, 256>>>(ei);

    k_aggz <<<gW, 256>>>(z);
    k_gemm1<<<gG, 128>>>(W1, b1);
    k_gemm2<<<gG, 128>>>(W2);
    k_agg2 <<<gW, 256>>>(b2, out);
}